// round 9
// baseline (speedup 1.0000x reference)
#include <cuda_runtime.h>

#define Bb 8
#define Tt 2048
#define Cc 1024
#define Hh 64
#define BT (Bb*Tt)

// q,v scratch pre-rounded tf32; k additionally DIM-PERMUTED (pairs (t,t+4) adjacent)
__device__ float g_q[BT*Hh];
__device__ float g_k[BT*Hh];
__device__ float g_v[BT*Hh];
// fused W, TRANSPOSED [n=192][k=1024], tf32 pre-rounded, k-pair-permuted per 8-group
__device__ float g_wt[192*Cc];
// split-KV partials
__device__ float g_pO[2*BT*Hh];
__device__ float g_pm[2*BT];
__device__ float g_pl[2*BT];

__device__ __forceinline__ float fast_exp2(float x){
    float y;
    asm("ex2.approx.ftz.f32 %0, %1;" : "=f"(y) : "f"(x));
    return y;
}
__device__ __forceinline__ unsigned f2tf(float f){
    unsigned r;
    asm("cvt.rna.tf32.f32 %0, %1;" : "=r"(r) : "f"(f));
    return r;
}
__device__ __forceinline__ void mma_tf32(float c[4], const unsigned a[4], const unsigned b[2]){
    asm volatile("mma.sync.aligned.m16n8k8.row.col.f32.tf32.tf32.f32 "
        "{%0,%1,%2,%3}, {%4,%5,%6,%7}, {%8,%9}, {%0,%1,%2,%3};"
        : "+f"(c[0]), "+f"(c[1]), "+f"(c[2]), "+f"(c[3])
        : "r"(a[0]), "r"(a[1]), "r"(a[2]), "r"(a[3]), "r"(b[0]), "r"(b[1]));
}
__device__ __forceinline__ void cp16(unsigned dst, const void* src){
    asm volatile("cp.async.cg.shared.global [%0], [%1], 16;" :: "r"(dst), "l"(src));
}
__device__ __forceinline__ void cp_commit(){ asm volatile("cp.async.commit_group;"); }
__device__ __forceinline__ void cp_wait0(){ asm volatile("cp.async.wait_group 0;"); }
__device__ __forceinline__ void cp_wait1(){ asm volatile("cp.async.wait_group 1;"); }
__device__ __forceinline__ void bar_sync(int id){
    asm volatile("bar.sync %0, 128;" :: "r"(id));
}

// ---------------------------------------------------------------------------
// One-shot W fuse+transpose+permute: g_wt[n][kperm] = tf32(W[k][n]),
// kperm = (k&~7) + 2*(k&3) + ((k>>2)&1)  (pairs (t,t+4) adjacent)
// ---------------------------------------------------------------------------
__global__ __launch_bounds__(256) void cvt_w_kernel(
    const float* __restrict__ Wk,
    const float* __restrict__ Wq,
    const float* __restrict__ Wv)
{
    const int idx = blockIdx.x * 256 + threadIdx.x;   // 192*1024 total
    const int n = idx >> 10;
    const int k = idx & 1023;
    const float* src = (n < 64) ? &Wk[(size_t)k * Hh + n]
                     : (n < 128) ? &Wq[(size_t)k * Hh + n - 64]
                                 : &Wv[(size_t)k * Hh + n - 128];
    const int kperm = (k & ~7) + 2 * (k & 3) + ((k >> 2) & 1);
    g_wt[(size_t)n * Cc + kperm] = __uint_as_float(f2tf(*src));
}

// ---------------------------------------------------------------------------
// Fused projection: [BT x 1024] @ W[1024 x 192]. 32x192 tile/block (512 blocks),
// 256 threads = 8 warps (2m x 4n), warp tile 16x48, 3 blocks/SM.
// x: registers -> transposed row-pair-permuted smem, a-frags = LDS.64, no cvt.
// W: cp.async direct from pre-converted g_wt, b-frags = LDS.64, no cvt.
// ---------------------------------------------------------------------------
#define PXW 40                 // xsT stride words (==8 mod 32), 32 slots used
#define PXS (32*PXW)           // 1280 words per stage (k=32 rows)
#define PWW 40                 // wsT row stride words (==8 mod 32)
#define PWS (192*PWW)          // 7680 words per stage
#define PROJ_SMEM ((2*PXS + 2*PWS)*4)   // 71680 B

__global__ __launch_bounds__(256, 3) void proj_kernel(const float* __restrict__ x)
{
    const int row0 = blockIdx.x * 32;
    const int tid  = threadIdx.x;
    const int warp = tid >> 5;
    const int lane = tid & 31;
    const int mw = warp >> 2;      // 0..1  -> rows mw*16 + (g, g+8)
    const int wn = warp & 3;       // 0..3  -> cols wn*48 ..
    const int g = lane >> 2;
    const int t = lane & 3;

    extern __shared__ float sm[];
    unsigned* const xsm = (unsigned*)sm;                 // 2 stages xsT
    unsigned* const wsm = (unsigned*)sm + 2 * PXS;       // 2 stages wsT
    const unsigned smb  = (unsigned)__cvta_generic_to_shared(sm);
    const unsigned wsmb = smb + 2u * PXS * 4u;

    float c[6][4];
#pragma unroll
    for (int nf = 0; nf < 6; nf++)
#pragma unroll
        for (int i = 0; i < 4; i++) c[nf][i] = 0.f;

    // x: 32 rows x 32 k = 256 float4, one per thread
    const int xr  = tid & 31;                       // row in tile
    const int xkg = tid >> 5;                       // k-group 0..7
    const int qr  = (xr & ~15) + 2 * (xr & 7) + ((xr >> 3) & 1);  // slot(row)

    float4 xv;
    auto ldg_x = [&](int kc){
        xv = *(const float4*)&x[(size_t)(row0 + xr) * Cc + kc + xkg * 4];
    };
    auto sts_x = [&](int s){
        unsigned* xs = xsm + s * PXS;
        xs[(xkg * 4 + 0) * PXW + qr] = f2tf(xv.x);
        xs[(xkg * 4 + 1) * PXW + qr] = f2tf(xv.y);
        xs[(xkg * 4 + 2) * PXW + qr] = f2tf(xv.z);
        xs[(xkg * 4 + 3) * PXW + qr] = f2tf(xv.w);
    };
    auto cp_w = [&](int kc, int s){
        const unsigned wb = wsmb + (unsigned)(s * PWS) * 4u;
#pragma unroll
        for (int u = 0; u < 6; u++) {
            int f = tid + 256 * u;                  // 1536 float4: 192 rows x 8 groups
            cp16(wb + (unsigned)((f >> 3) * PWW + (f & 7) * 4) * 4u,
                 &g_wt[(size_t)(f >> 3) * Cc + kc + (f & 7) * 4]);
        }
        cp_commit();
    };

    ldg_x(0); cp_w(0, 0); sts_x(0);

    for (int it = 0; it < Cc / 32; it++) {
        cp_wait0();
        __syncthreads();
        const bool more = (it + 1 < Cc / 32);
        if (more) { ldg_x((it + 1) * 32); cp_w((it + 1) * 32, (it + 1) & 1); }

        const unsigned* xs = xsm + (it & 1) * PXS;
        const unsigned* ws = wsm + (it & 1) * PWS;
#pragma unroll
        for (int ks = 0; ks < 4; ks++) {
            const int k0 = ks * 8;
            uint2 a01 = *(const uint2*)&xs[(k0 + t) * PXW + mw * 16 + 2 * g];
            uint2 a23 = *(const uint2*)&xs[(k0 + t + 4) * PXW + mw * 16 + 2 * g];
            unsigned a[4] = { a01.x, a01.y, a23.x, a23.y };
#pragma unroll
            for (int nf = 0; nf < 6; nf++) {
                uint2 bb = *(const uint2*)&ws[(wn * 48 + nf * 8 + g) * PWW + k0 + 2 * t];
                unsigned b[2] = { bb.x, bb.y };
                mma_tf32(c[nf], a, b);
            }
        }
        if (more) sts_x((it + 1) & 1);
    }

    // epilogue: pre-round tf32; k gets dim permutation p(o)=2*(o&3)+(o>>2)
    const size_t r0 = row0 + mw * 16 + g;
#pragma unroll
    for (int nf = 0; nf < 6; nf++) {
        const int col = wn * 48 + nf * 8 + 2 * t;
        float v0 = __uint_as_float(f2tf(c[nf][0]));
        float v1 = __uint_as_float(f2tf(c[nf][1]));
        float v2 = __uint_as_float(f2tf(c[nf][2]));
        float v3 = __uint_as_float(f2tf(c[nf][3]));
        if (col < 64) {            // k: permuted scatter
            const int base = col & ~7, o = col & 7;
            const int p0 = base + 2 * (o & 3) + (o >> 2);
            const int p1 = base + 2 * ((o + 1) & 3) + ((o + 1) >> 2);
            g_k[r0 * Hh + p0] = v0;       g_k[r0 * Hh + p1] = v1;
            g_k[(r0 + 8) * Hh + p0] = v2; g_k[(r0 + 8) * Hh + p1] = v3;
        } else {
            float* po = (col < 128) ? g_q : g_v;
            const int l = (col < 128) ? col - 64 : col - 128;
            *(float2*)&po[r0 * Hh + l]       = make_float2(v0, v1);
            *(float2*)&po[(r0 + 8) * Hh + l] = make_float2(v2, v3);
        }
    }
}

// ---------------------------------------------------------------------------
// Flash attention, split-KV x2 at block level + dual group split in block.
// grid (32, 2, 8), 256 threads, 2 blocks/SM (Q in smem frees registers).
// Q staged in transposed row-pair-permuted smem (scale+tf32 folded at store).
// Writes unnormalized partials (O', m, l); merge_kernel finalizes.
// ---------------------------------------------------------------------------
#define AW 72                  // K and V stride words (==8 mod 32)
#define ATILE (64*AW)          // 4608 words
#define QW 72
#define QTILE (64*QW)          // 4608 words
#define ATTN_SMEM ((4*ATILE + QTILE)*4)   // 92160 B

__global__ __launch_bounds__(256, 2) void attn_kernel()
{
    const int qt   = (int)gridDim.x - 1 - (int)blockIdx.x;   // heavy first
    const int half = blockIdx.y;
    const int b    = blockIdx.z;
    const int q0   = qt * 64;
    const int tid  = threadIdx.x;
    const int warp = tid >> 5;
    const int lane = tid & 31;
    const int group = warp >> 2;
    const int wl   = warp & 3;
    const int wr0  = wl * 16;
    const int g = lane >> 2;
    const int t = lane & 3;
    const int gtid = tid & 127;

    extern __shared__ float sm[];
    const unsigned smb = (unsigned)__cvta_generic_to_shared(sm);

    const float scale = 0.125f * 1.44269504088896340736f;

    const int src0 = (lane & ~3) | (t >> 1);
    const int src2 = src0 + 2;
    const int lrow = gtid >> 4, lc4 = (gtid & 15) * 4;

    const unsigned kb = smb + (unsigned)(group * 2 * ATILE) * 4u;
    const unsigned vb = kb + ATILE * 4u;

    auto load_k = [&](int n0){
        const float* kp = g_k + ((size_t)b * Tt + n0) * Hh;
#pragma unroll
        for (int u = 0; u < 8; u++) {
            int row = lrow + 8 * u;
            cp16(kb + (unsigned)(row * AW + lc4) * 4u, kp + (size_t)row * Hh + lc4);
        }
        cp_commit();
    };
    auto load_v = [&](int n0){
        const float* vp = g_v + ((size_t)b * Tt + n0) * Hh;
#pragma unroll
        for (int u = 0; u < 8; u++) {
            int row = lrow + 8 * u;
            cp16(vb + (unsigned)(row * AW + lc4) * 4u, vp + (size_t)row * Hh + lc4);
        }
        cp_commit();
    };

    const int nt = qt + 1;
    const int s  = (half == 0) ? 0 : (nt + 1) / 2;
    const int e  = (half == 0) ? (nt + 1) / 2 : nt;
    const int ng = (e - s > group) ? ((e - s - group + 1) >> 1) : 0;

    if (ng > 0) { load_k((s + group) * 64); load_v((s + group) * 64); }

    // stage Q tile: qsT[k][slot(row)] with scale + tf32 folded (overlaps K/V cp.async)
    unsigned* const qs = (unsigned*)sm + 4 * ATILE;
    {
        const int qrw  = tid & 63;                    // row in tile
        const int qkg  = tid >> 6;                    // 0..3: k-range qkg*16..
        const int qslt = (qrw & ~15) + 2 * (qrw & 7) + ((qrw >> 3) & 1);
        const float* qp = g_q + ((size_t)b * Tt + q0 + qrw) * Hh;
#pragma unroll
        for (int j = 0; j < 4; j++) {
            float4 v = *(const float4*)&qp[qkg * 16 + j * 4];
            qs[(qkg * 16 + j * 4 + 0) * QW + qslt] = f2tf(v.x * scale);
            qs[(qkg * 16 + j * 4 + 1) * QW + qslt] = f2tf(v.y * scale);
            qs[(qkg * 16 + j * 4 + 2) * QW + qslt] = f2tf(v.z * scale);
            qs[(qkg * 16 + j * 4 + 3) * QW + qslt] = f2tf(v.w * scale);
        }
    }
    __syncthreads();

    float oc[8][4];
#pragma unroll
    for (int nf = 0; nf < 8; nf++)
#pragma unroll
        for (int i = 0; i < 4; i++) oc[nf][i] = 0.f;
    float m0 = -1e30f, m1 = -1e30f, l0 = 0.f, l1 = 0.f;

    const unsigned* Ks = (const unsigned*)sm + group * 2 * ATILE;
    const unsigned* Vs = Ks + ATILE;

    for (int j = 0; j < ng; j++) {
        const int tile = s + 2 * j + group;

        cp_wait1();               // own K chunks ready
        bar_sync(1 + group);      // everyone's K ready / prev Vs consumers done

        float sc[8][4];
#pragma unroll
        for (int nf = 0; nf < 8; nf++)
#pragma unroll
            for (int i = 0; i < 4; i++) sc[nf][i] = 0.f;
#pragma unroll
        for (int kc = 0; kc < 8; kc++) {
            uint2 a01 = *(const uint2*)&qs[(kc * 8 + t) * QW + wr0 + 2 * g];
            uint2 a23 = *(const uint2*)&qs[(kc * 8 + t + 4) * QW + wr0 + 2 * g];
            unsigned a[4] = { a01.x, a01.y, a23.x, a23.y };
#pragma unroll
            for (int nf = 0; nf < 8; nf++) {
                uint2 kk = *(const uint2*)&Ks[(nf * 8 + g) * AW + kc * 8 + 2 * t];
                unsigned bk[2] = { kk.x, kk.y };
                mma_tf32(sc[nf], a, bk);
            }
        }
        bar_sync(1 + group);      // Ks consumed
        if (j + 1 < ng) load_k((tile + 2) * 64);

        if (tile == qt) {
#pragma unroll
            for (int nf = 0; nf < 8; nf++) {
                const int kl = nf * 8 + 2 * t;
                if (kl     > wr0 + g)     sc[nf][0] = -1e30f;
                if (kl + 1 > wr0 + g)     sc[nf][1] = -1e30f;
                if (kl     > wr0 + g + 8) sc[nf][2] = -1e30f;
                if (kl + 1 > wr0 + g + 8) sc[nf][3] = -1e30f;
            }
        }

        float mx0 = -1e30f, mx1 = -1e30f;
#pragma unroll
        for (int nf = 0; nf < 8; nf++) {
            mx0 = fmaxf(mx0, fmaxf(sc[nf][0], sc[nf][1]));
            mx1 = fmaxf(mx1, fmaxf(sc[nf][2], sc[nf][3]));
        }
        mx0 = fmaxf(mx0, __shfl_xor_sync(0xffffffffu, mx0, 1));
        mx0 = fmaxf(mx0, __shfl_xor_sync(0xffffffffu, mx0, 2));
        mx1 = fmaxf(mx1, __shfl_xor_sync(0xffffffffu, mx1, 1));
        mx1 = fmaxf(mx1, __shfl_xor_sync(0xffffffffu, mx1, 2));

        const float m0n = fmaxf(m0, mx0);
        const float m1n = fmaxf(m1, mx1);
        const float corr0 = fast_exp2(m0 - m0n);
        const float corr1 = fast_exp2(m1 - m1n);
        l0 *= corr0; l1 *= corr1;
#pragma unroll
        for (int nf = 0; nf < 8; nf++) {
            oc[nf][0] *= corr0; oc[nf][1] *= corr0;
            oc[nf][2] *= corr1; oc[nf][3] *= corr1;
        }
#pragma unroll
        for (int nf = 0; nf < 8; nf++) {
            float p0 = fast_exp2(sc[nf][0] - m0n);
            float p1 = fast_exp2(sc[nf][1] - m0n);
            float p2 = fast_exp2(sc[nf][2] - m1n);
            float p3 = fast_exp2(sc[nf][3] - m1n);
            l0 += p0 + p1;
            l1 += p2 + p3;
            sc[nf][0] = __uint_as_float(f2tf(p0));
            sc[nf][1] = __uint_as_float(f2tf(p1));
            sc[nf][2] = __uint_as_float(f2tf(p2));
            sc[nf][3] = __uint_as_float(f2tf(p3));
        }
        m0 = m0n; m1 = m1n;

        cp_wait1();               // own V chunks ready
        bar_sync(1 + group);      // everyone's V ready

#pragma unroll
        for (int kc = 0; kc < 8; kc++) {
            unsigned a[4];
            {
                unsigned p0 = __float_as_uint(sc[kc][0]);
                unsigned p1 = __float_as_uint(sc[kc][1]);
                unsigned p2 = __float_as_uint(sc[kc][2]);
                unsigned p3 = __float_as_uint(sc[kc][3]);
                unsigned e0 = __shfl_sync(0xffffffffu, p0, src0);
                unsigned o0 = __shfl_sync(0xffffffffu, p1, src0);
                a[0] = (t & 1) ? o0 : e0;
                unsigned e1 = __shfl_sync(0xffffffffu, p2, src0);
                unsigned o1 = __shfl_sync(0xffffffffu, p3, src0);
                a[1] = (t & 1) ? o1 : e1;
                unsigned e2 = __shfl_sync(0xffffffffu, p0, src2);
                unsigned o2 = __shfl_sync(0xffffffffu, p1, src2);
                a[2] = (t & 1) ? o2 : e2;
                unsigned e3 = __shfl_sync(0xffffffffu, p2, src2);
                unsigned o3 = __shfl_sync(0xffffffffu, p3, src2);
                a[3] = (t & 1) ? o3 : e3;
            }
#pragma unroll
            for (int nf = 0; nf < 8; nf++) {
                unsigned bv[2] = { Vs[(kc * 8 + t) * AW + nf * 8 + g],
                                   Vs[(kc * 8 + t + 4) * AW + nf * 8 + g] };
                mma_tf32(oc[nf], a, bv);
            }
        }
        bar_sync(1 + group);      // Vs consumed
        if (j + 1 < ng) load_v((tile + 2) * 64);
    }

    // ---- merge group partials, write block partial (unnormalized) ----
    __syncthreads();
    if (group == 1) {
        float* st = sm + (wl * 32 + lane) * 37;
#pragma unroll
        for (int nf = 0; nf < 8; nf++)
#pragma unroll
            for (int i = 0; i < 4; i++) st[nf * 4 + i] = oc[nf][i];
        st[32] = m0; st[33] = m1; st[34] = l0; st[35] = l1;
    }
    __syncthreads();
    if (group == 0) {
        const float* st = sm + (wl * 32 + lane) * 37;
        const float mb0 = st[32], mb1 = st[33], lb0 = st[34], lb1 = st[35];
        const float M0 = fmaxf(m0, mb0), M1 = fmaxf(m1, mb1);
        const float ca0 = fast_exp2(m0 - M0), cb0 = fast_exp2(mb0 - M0);
        const float ca1 = fast_exp2(m1 - M1), cb1 = fast_exp2(mb1 - M1);
        l0 = l0 * ca0 + lb0 * cb0;
        l1 = l1 * ca1 + lb1 * cb1;
#pragma unroll
        for (int nf = 0; nf < 8; nf++) {
            oc[nf][0] = oc[nf][0] * ca0 + st[nf * 4 + 0] * cb0;
            oc[nf][1] = oc[nf][1] * ca0 + st[nf * 4 + 1] * cb0;
            oc[nf][2] = oc[nf][2] * ca1 + st[nf * 4 + 2] * cb1;
            oc[nf][3] = oc[nf][3] * ca1 + st[nf * 4 + 3] * cb1;
        }
        l0 += __shfl_xor_sync(0xffffffffu, l0, 1);
        l0 += __shfl_xor_sync(0xffffffffu, l0, 2);
        l1 += __shfl_xor_sync(0xffffffffu, l1, 1);
        l1 += __shfl_xor_sync(0xffffffffu, l1, 2);

        const size_t row = (size_t)b * Tt + q0 + wr0 + g;
        float* po = g_pO + ((size_t)half * BT + row) * Hh;
#pragma unroll
        for (int nf = 0; nf < 8; nf++) {
            const int col = nf * 8 + 2 * t;
            *(float2*)&po[col]            = make_float2(oc[nf][0], oc[nf][1]);
            *(float2*)&po[8 * Hh + col]   = make_float2(oc[nf][2], oc[nf][3]);
        }
        if (t == 0) {
            g_pm[half * BT + row] = fmaxf(M0, m0);
            g_pl[half * BT + row] = l0;
            g_pm[half * BT + row + 8] = fmaxf(M1, m1);
            g_pl[half * BT + row + 8] = l1;
        }
    }
}

// ---------------------------------------------------------------------------
// Merge the two KV halves + normalize. One float4 of one row per thread.
// ---------------------------------------------------------------------------
__global__ __launch_bounds__(256) void merge_kernel(float* __restrict__ out)
{
    const int idx = blockIdx.x * 256 + threadIdx.x;   // BT*16 total
    const int row = idx >> 4;
    const int d4  = idx & 15;
    const float ma = g_pm[row],      mb = g_pm[BT + row];
    const float la = g_pl[row],      lb = g_pl[BT + row];
    const float M  = fmaxf(ma, mb);
    float ca = fast_exp2(ma - M);
    float cb = fast_exp2(mb - M);
    const float inv = 1.0f / (la * ca + lb * cb);
    ca *= inv; cb *= inv;
    float4 va = ((const float4*)&g_pO[(size_t)row * Hh])[d4];
    float4 vb = ((const float4*)&g_pO[(size_t)(BT + row) * Hh])[d4];
    ((float4*)&out[(size_t)row * Hh])[d4] =
        make_float4(va.x * ca + vb.x * cb, va.y * ca + vb.y * cb,
                    va.z * ca + vb.z * cb, va.w * ca + vb.w * cb);
}

extern "C" void kernel_launch(void* const* d_in, const int* in_sizes, int n_in,
                              void* d_out, int out_size)
{
    const float* x  = (const float*)d_in[0];
    const float* Wk = (const float*)d_in[1];
    const float* Wq = (const float*)d_in[2];
    const float* Wv = (const float*)d_in[3];
    float* out = (float*)d_out;

    cudaFuncSetAttribute(proj_kernel, cudaFuncAttributeMaxDynamicSharedMemorySize, PROJ_SMEM);
    cudaFuncSetAttribute(attn_kernel, cudaFuncAttributeMaxDynamicSharedMemorySize, ATTN_SMEM);

    cvt_w_kernel<<<192 * Cc / 256, 256>>>(Wk, Wq, Wv);

    proj_kernel<<<BT / 32, 256, PROJ_SMEM>>>(x);

    dim3 ag(Tt / 64, 2, Bb);
    attn_kernel<<<ag, 256, ATTN_SMEM>>>();

    merge_kernel<<<BT * 16 / 256, 256>>>(out);
}

// round 10
// speedup vs baseline: 1.2142x; 1.2142x over previous
#include <cuda_runtime.h>

#define Bb 8
#define Tt 2048
#define Cc 1024
#define Hh 64
#define BT (Bb*Tt)

// q,v scratch pre-rounded tf32; k additionally DIM-PERMUTED (pairs (t,t+4) adjacent)
__device__ float g_q[BT*Hh];
__device__ float g_k[BT*Hh];
__device__ float g_v[BT*Hh];
// fused W, TRANSPOSED [n=192][k=1024], tf32 pre-rounded, k-pair-permuted per 8-group
__device__ float g_wt[192*Cc];
// split-KV partials
__device__ float g_pO[2*BT*Hh];
__device__ float g_pm[2*BT];
__device__ float g_pl[2*BT];

__device__ __forceinline__ float fast_exp2(float x){
    float y;
    asm("ex2.approx.ftz.f32 %0, %1;" : "=f"(y) : "f"(x));
    return y;
}
__device__ __forceinline__ unsigned f2tf(float f){
    unsigned r;
    asm("cvt.rna.tf32.f32 %0, %1;" : "=r"(r) : "f"(f));
    return r;
}
__device__ __forceinline__ void mma_tf32(float c[4], const unsigned a[4], const unsigned b[2]){
    asm volatile("mma.sync.aligned.m16n8k8.row.col.f32.tf32.tf32.f32 "
        "{%0,%1,%2,%3}, {%4,%5,%6,%7}, {%8,%9}, {%0,%1,%2,%3};"
        : "+f"(c[0]), "+f"(c[1]), "+f"(c[2]), "+f"(c[3])
        : "r"(a[0]), "r"(a[1]), "r"(a[2]), "r"(a[3]), "r"(b[0]), "r"(b[1]));
}
__device__ __forceinline__ void cp16(unsigned dst, const void* src){
    asm volatile("cp.async.cg.shared.global [%0], [%1], 16;" :: "r"(dst), "l"(src));
}
__device__ __forceinline__ void cp_commit(){ asm volatile("cp.async.commit_group;"); }
__device__ __forceinline__ void cp_wait1(){ asm volatile("cp.async.wait_group 1;"); }
__device__ __forceinline__ void bar_sync(int id){
    asm volatile("bar.sync %0, 128;" :: "r"(id));
}

// ---------------------------------------------------------------------------
// One-shot W fuse+transpose+permute: g_wt[n][kperm] = tf32(W[k][n]),
// kperm = (k&~7) + 2*(k&3) + ((k>>2)&1)  (pairs (t,t+4) adjacent)
// ---------------------------------------------------------------------------
__global__ __launch_bounds__(256) void cvt_w_kernel(
    const float* __restrict__ Wk,
    const float* __restrict__ Wq,
    const float* __restrict__ Wv)
{
    const int idx = blockIdx.x * 256 + threadIdx.x;   // 192*1024 total
    const int n = idx >> 10;
    const int k = idx & 1023;
    const float* src = (n < 64) ? &Wk[(size_t)k * Hh + n]
                     : (n < 128) ? &Wq[(size_t)k * Hh + n - 64]
                                 : &Wv[(size_t)k * Hh + n - 128];
    const int kperm = (k & ~7) + 2 * (k & 3) + ((k >> 2) & 1);
    g_wt[(size_t)n * Cc + kperm] = __uint_as_float(f2tf(*src));
}

// ---------------------------------------------------------------------------
// Fused projection: [BT x 1024] @ W[1024 x 192]. 64x192 tile/block,
// 256 threads = 8 warps (2m x 4n), warp tile 32x48.
// x: registers -> transposed row-pair-permuted smem, a-frags = LDS.64, no cvt.
// W: g_wt transposed+permuted -> b-frags = LDS.64, no cvt.
// ---------------------------------------------------------------------------
#define PXW 72                 // xsT stride words (==8 mod 32)
#define PXS (32*PXW)           // 2304 words per stage
#define PWW 40                 // wsT stride words (==8 mod 32)
#define PWS (192*PWW)          // 7680 words per stage
#define PROJ_SMEM ((2*PXS + 2*PWS)*4)   // 79872 B

__global__ __launch_bounds__(256, 2) void proj_kernel(const float* __restrict__ x)
{
    const int row0 = blockIdx.x * 64;
    const int tid  = threadIdx.x;
    const int warp = tid >> 5;
    const int lane = tid & 31;
    const int mw = warp >> 2;      // 0..1
    const int wn = warp & 3;       // 0..3
    const int g = lane >> 2;
    const int t = lane & 3;

    extern __shared__ float sm[];
    unsigned* const xsm = (unsigned*)sm;                 // 2 stages xsT
    unsigned* const wsm = (unsigned*)sm + 2 * PXS;       // 2 stages wsT

    float c[2][6][4];
#pragma unroll
    for (int mf = 0; mf < 2; mf++)
#pragma unroll
        for (int nf = 0; nf < 6; nf++)
#pragma unroll
            for (int i = 0; i < 4; i++) c[mf][nf][i] = 0.f;

    const int xr  = tid & 63;
    const int xcg = tid >> 6;
    const int qr  = (xr & ~15) + 2 * (xr & 7) + ((xr >> 3) & 1);   // slot(r)
    const int wf0 = tid;

    float4 xv[2];
    uint4  wv[6];

    auto ldg_x = [&](int kc){
#pragma unroll
        for (int u = 0; u < 2; u++) {
            int cc = (xcg + 4 * u) * 4;
            xv[u] = *(const float4*)&x[(size_t)(row0 + xr) * Cc + kc + cc];
        }
    };
    auto sts_x = [&](int s){
        unsigned* xs = xsm + s * PXS;
#pragma unroll
        for (int u = 0; u < 2; u++) {
            int cc = (xcg + 4 * u) * 4;
            xs[(cc + 0) * PXW + qr] = f2tf(xv[u].x);
            xs[(cc + 1) * PXW + qr] = f2tf(xv[u].y);
            xs[(cc + 2) * PXW + qr] = f2tf(xv[u].z);
            xs[(cc + 3) * PXW + qr] = f2tf(xv[u].w);
        }
    };
    auto ldg_w = [&](int kc){
#pragma unroll
        for (int u = 0; u < 6; u++) {
            int f = wf0 + 256 * u;
            wv[u] = *(const uint4*)&g_wt[(size_t)(f >> 3) * Cc + kc + (f & 7) * 4];
        }
    };
    auto sts_w = [&](int s){
        unsigned* ws = wsm + s * PWS;
#pragma unroll
        for (int u = 0; u < 6; u++) {
            int f = wf0 + 256 * u;
            *(uint4*)&ws[(f >> 3) * PWW + (f & 7) * 4] = wv[u];
        }
    };

    ldg_x(0); ldg_w(0);
    sts_x(0); sts_w(0);

    for (int it = 0; it < Cc / 32; it++) {
        __syncthreads();
        const bool more = (it + 1 < Cc / 32);
        if (more) { ldg_x((it + 1) * 32); ldg_w((it + 1) * 32); }

        const unsigned* xs = xsm + (it & 1) * PXS;
        const unsigned* ws = wsm + (it & 1) * PWS;
#pragma unroll
        for (int ks = 0; ks < 4; ks++) {
            const int k0 = ks * 8;
            unsigned b[6][2];
#pragma unroll
            for (int nf = 0; nf < 6; nf++) {
                uint2 bb = *(const uint2*)&ws[(wn * 48 + nf * 8 + g) * PWW + k0 + 2 * t];
                b[nf][0] = bb.x; b[nf][1] = bb.y;
            }
#pragma unroll
            for (int mf = 0; mf < 2; mf++) {
                const int sbase = mw * 32 + mf * 16 + 2 * g;
                uint2 a01 = *(const uint2*)&xs[(k0 + t) * PXW + sbase];
                uint2 a23 = *(const uint2*)&xs[(k0 + t + 4) * PXW + sbase];
                unsigned a[4] = { a01.x, a01.y, a23.x, a23.y };
#pragma unroll
                for (int nf = 0; nf < 6; nf++) mma_tf32(c[mf][nf], a, b[nf]);
            }
        }
        if (more) { sts_x((it + 1) & 1); sts_w((it + 1) & 1); }
    }

    // epilogue: pre-round tf32; k gets dim permutation p(o)=2*(o&3)+(o>>2)
#pragma unroll
    for (int mf = 0; mf < 2; mf++) {
        const size_t r0 = row0 + mw * 32 + mf * 16 + g;
#pragma unroll
        for (int nf = 0; nf < 6; nf++) {
            const int col = wn * 48 + nf * 8 + 2 * t;
            float v0 = __uint_as_float(f2tf(c[mf][nf][0]));
            float v1 = __uint_as_float(f2tf(c[mf][nf][1]));
            float v2 = __uint_as_float(f2tf(c[mf][nf][2]));
            float v3 = __uint_as_float(f2tf(c[mf][nf][3]));
            if (col < 64) {            // k: permuted scatter
                const int base = col & ~7, o = col & 7;
                const int p0 = base + 2 * (o & 3) + (o >> 2);
                const int p1 = base + 2 * ((o + 1) & 3) + ((o + 1) >> 2);
                g_k[r0 * Hh + p0] = v0;       g_k[r0 * Hh + p1] = v1;
                g_k[(r0 + 8) * Hh + p0] = v2; g_k[(r0 + 8) * Hh + p1] = v3;
            } else {
                float* po = (col < 128) ? g_q : g_v;
                const int l = (col < 128) ? col - 64 : col - 128;
                *(float2*)&po[r0 * Hh + l]       = make_float2(v0, v1);
                *(float2*)&po[(r0 + 8) * Hh + l] = make_float2(v2, v3);
            }
        }
    }
}

// ---------------------------------------------------------------------------
// Flash attention, split-KV x2 at block level + dual group split in block.
// grid (32, 2, 8), 256 threads. Single-stage smem, staged K/V cp.async.
// PV uses P's C-layout registers DIRECTLY as A operand ({c0,c2,c1,c3}) with
// V b-frag rows (2t, 2t+1): zero shuffles (k-permutation invariance).
// Writes unnormalized partials (O', m, l); merge_kernel finalizes.
// ---------------------------------------------------------------------------
#define AW 72                  // K and V stride words (==8 mod 32)
#define ATILE (64*AW)          // 4608 words
#define ATTN_SMEM (4*ATILE*4)  // 73728 B  (2 groups x (K,V))

__global__ __launch_bounds__(256, 2) void attn_kernel()
{
    const int qt   = (int)gridDim.x - 1 - (int)blockIdx.x;   // heavy first
    const int half = blockIdx.y;
    const int b    = blockIdx.z;
    const int q0   = qt * 64;
    const int tid  = threadIdx.x;
    const int warp = tid >> 5;
    const int lane = tid & 31;
    const int group = warp >> 2;
    const int wl   = warp & 3;
    const int wr0  = wl * 16;
    const int g = lane >> 2;
    const int t = lane & 3;
    const int gtid = tid & 127;

    extern __shared__ float sm[];
    const unsigned smb = (unsigned)__cvta_generic_to_shared(sm);

    const float scale = 0.125f * 1.44269504088896340736f;

    unsigned qa[8][4];
    {
        const float* qp = g_q + ((size_t)b * Tt + q0 + wr0) * Hh;
#pragma unroll
        for (int kc = 0; kc < 8; kc++) {
            qa[kc][0] = f2tf(qp[g * Hh + kc * 8 + t] * scale);
            qa[kc][1] = f2tf(qp[(g + 8) * Hh + kc * 8 + t] * scale);
            qa[kc][2] = f2tf(qp[g * Hh + kc * 8 + t + 4] * scale);
            qa[kc][3] = f2tf(qp[(g + 8) * Hh + kc * 8 + t + 4] * scale);
        }
    }

    float oc[8][4];
#pragma unroll
    for (int nf = 0; nf < 8; nf++)
#pragma unroll
        for (int i = 0; i < 4; i++) oc[nf][i] = 0.f;
    float m0 = -1e30f, m1 = -1e30f, l0 = 0.f, l1 = 0.f;

    const int lrow = gtid >> 4, lc4 = (gtid & 15) * 4;

    const unsigned kb = smb + (unsigned)(group * 2 * ATILE) * 4u;
    const unsigned vb = kb + ATILE * 4u;

    auto load_k = [&](int n0){
        const float* kp = g_k + ((size_t)b * Tt + n0) * Hh;
#pragma unroll
        for (int u = 0; u < 8; u++) {
            int row = lrow + 8 * u;
            cp16(kb + (unsigned)(row * AW + lc4) * 4u, kp + (size_t)row * Hh + lc4);
        }
        cp_commit();
    };
    auto load_v = [&](int n0){
        const float* vp = g_v + ((size_t)b * Tt + n0) * Hh;
#pragma unroll
        for (int u = 0; u < 8; u++) {
            int row = lrow + 8 * u;
            cp16(vb + (unsigned)(row * AW + lc4) * 4u, vp + (size_t)row * Hh + lc4);
        }
        cp_commit();
    };

    const int nt = qt + 1;
    const int s  = (half == 0) ? 0 : (nt + 1) / 2;
    const int e  = (half == 0) ? (nt + 1) / 2 : nt;
    const int ng = (e - s > group) ? ((e - s - group + 1) >> 1) : 0;

    if (ng > 0) { load_k((s + group) * 64); load_v((s + group) * 64); }

    const unsigned* Ks = (const unsigned*)sm + group * 2 * ATILE;
    const unsigned* Vs = Ks + ATILE;

    for (int j = 0; j < ng; j++) {
        const int tile = s + 2 * j + group;

        cp_wait1();               // own K chunks ready
        bar_sync(1 + group);      // everyone's K ready / prev Vs consumers done

        float sc[8][4];
#pragma unroll
        for (int nf = 0; nf < 8; nf++)
#pragma unroll
            for (int i = 0; i < 4; i++) sc[nf][i] = 0.f;
#pragma unroll
        for (int kc = 0; kc < 8; kc++) {
#pragma unroll
            for (int nf = 0; nf < 8; nf++) {
                uint2 kk = *(const uint2*)&Ks[(nf * 8 + g) * AW + kc * 8 + 2 * t];
                unsigned bk[2] = { kk.x, kk.y };
                mma_tf32(sc[nf], qa[kc], bk);
            }
        }
        bar_sync(1 + group);      // Ks consumed
        if (j + 1 < ng) load_k((tile + 2) * 64);

        if (tile == qt) {
#pragma unroll
            for (int nf = 0; nf < 8; nf++) {
                const int kl = nf * 8 + 2 * t;
                if (kl     > wr0 + g)     sc[nf][0] = -1e30f;
                if (kl + 1 > wr0 + g)     sc[nf][1] = -1e30f;
                if (kl     > wr0 + g + 8) sc[nf][2] = -1e30f;
                if (kl + 1 > wr0 + g + 8) sc[nf][3] = -1e30f;
            }
        }

        float mx0 = -1e30f, mx1 = -1e30f;
#pragma unroll
        for (int nf = 0; nf < 8; nf++) {
            mx0 = fmaxf(mx0, fmaxf(sc[nf][0], sc[nf][1]));
            mx1 = fmaxf(mx1, fmaxf(sc[nf][2], sc[nf][3]));
        }
        mx0 = fmaxf(mx0, __shfl_xor_sync(0xffffffffu, mx0, 1));
        mx0 = fmaxf(mx0, __shfl_xor_sync(0xffffffffu, mx0, 2));
        mx1 = fmaxf(mx1, __shfl_xor_sync(0xffffffffu, mx1, 1));
        mx1 = fmaxf(mx1, __shfl_xor_sync(0xffffffffu, mx1, 2));

        const float m0n = fmaxf(m0, mx0);
        const float m1n = fmaxf(m1, mx1);
        const float corr0 = fast_exp2(m0 - m0n);
        const float corr1 = fast_exp2(m1 - m1n);
        l0 *= corr0; l1 *= corr1;
#pragma unroll
        for (int nf = 0; nf < 8; nf++) {
            oc[nf][0] *= corr0; oc[nf][1] *= corr0;
            oc[nf][2] *= corr1; oc[nf][3] *= corr1;
        }
        unsigned pu[8][4];    // A-operand order {c0,c2,c1,c3}, tf32
#pragma unroll
        for (int nf = 0; nf < 8; nf++) {
            float p0 = fast_exp2(sc[nf][0] - m0n);
            float p1 = fast_exp2(sc[nf][1] - m0n);
            float p2 = fast_exp2(sc[nf][2] - m1n);
            float p3 = fast_exp2(sc[nf][3] - m1n);
            l0 += p0 + p1;
            l1 += p2 + p3;
            pu[nf][0] = f2tf(p0);
            pu[nf][1] = f2tf(p2);   // row g+8, key 2t   (A slot k=t)
            pu[nf][2] = f2tf(p1);   // row g,   key 2t+1 (A slot k=t+4)
            pu[nf][3] = f2tf(p3);
        }
        m0 = m0n; m1 = m1n;

        cp_wait1();               // own V chunks ready
        bar_sync(1 + group);      // everyone's V ready

        // O += P V : P C-layout direct as A; V b-frags from rows (2t, 2t+1)
#pragma unroll
        for (int kc = 0; kc < 8; kc++) {
#pragma unroll
            for (int nf = 0; nf < 8; nf++) {
                unsigned bv[2] = { Vs[(kc * 8 + 2 * t)     * AW + nf * 8 + g],
                                   Vs[(kc * 8 + 2 * t + 1) * AW + nf * 8 + g] };
                mma_tf32(oc[nf], pu[kc], bv);
            }
        }
        bar_sync(1 + group);      // Vs consumed
        if (j + 1 < ng) load_v((tile + 2) * 64);
    }

    // ---- merge group partials, write block partial (unnormalized) ----
    __syncthreads();
    if (group == 1) {
        float* st = sm + (wl * 32 + lane) * 37;
#pragma unroll
        for (int nf = 0; nf < 8; nf++)
#pragma unroll
            for (int i = 0; i < 4; i++) st[nf * 4 + i] = oc[nf][i];
        st[32] = m0; st[33] = m1; st[34] = l0; st[35] = l1;
    }
    __syncthreads();
    if (group == 0) {
        const float* st = sm + (wl * 32 + lane) * 37;
        const float mb0 = st[32], mb1 = st[33], lb0 = st[34], lb1 = st[35];
        const float M0 = fmaxf(m0, mb0), M1 = fmaxf(m1, mb1);
        const float ca0 = fast_exp2(m0 - M0), cb0 = fast_exp2(mb0 - M0);
        const float ca1 = fast_exp2(m1 - M1), cb1 = fast_exp2(mb1 - M1);
        l0 = l0 * ca0 + lb0 * cb0;
        l1 = l1 * ca1 + lb1 * cb1;
#pragma unroll
        for (int nf = 0; nf < 8; nf++) {
            oc[nf][0] = oc[nf][0] * ca0 + st[nf * 4 + 0] * cb0;
            oc[nf][1] = oc[nf][1] * ca0 + st[nf * 4 + 1] * cb0;
            oc[nf][2] = oc[nf][2] * ca1 + st[nf * 4 + 2] * cb1;
            oc[nf][3] = oc[nf][3] * ca1 + st[nf * 4 + 3] * cb1;
        }
        l0 += __shfl_xor_sync(0xffffffffu, l0, 1);
        l0 += __shfl_xor_sync(0xffffffffu, l0, 2);
        l1 += __shfl_xor_sync(0xffffffffu, l1, 1);
        l1 += __shfl_xor_sync(0xffffffffu, l1, 2);

        const size_t row = (size_t)b * Tt + q0 + wr0 + g;
        float* po = g_pO + ((size_t)half * BT + row) * Hh;
#pragma unroll
        for (int nf = 0; nf < 8; nf++) {
            const int col = nf * 8 + 2 * t;
            *(float2*)&po[col]            = make_float2(oc[nf][0], oc[nf][1]);
            *(float2*)&po[8 * Hh + col]   = make_float2(oc[nf][2], oc[nf][3]);
        }
        if (t == 0) {
            g_pm[half * BT + row] = fmaxf(M0, m0);
            g_pl[half * BT + row] = l0;
            g_pm[half * BT + row + 8] = fmaxf(M1, m1);
            g_pl[half * BT + row + 8] = l1;
        }
    }
}

// ---------------------------------------------------------------------------
// Merge the two KV halves + normalize. One float4 of one row per thread.
// ---------------------------------------------------------------------------
__global__ __launch_bounds__(256) void merge_kernel(float* __restrict__ out)
{
    const int idx = blockIdx.x * 256 + threadIdx.x;   // BT*16 total
    const int row = idx >> 4;
    const int d4  = idx & 15;
    const float ma = g_pm[row],      mb = g_pm[BT + row];
    const float la = g_pl[row],      lb = g_pl[BT + row];
    const float M  = fmaxf(ma, mb);
    float ca = fast_exp2(ma - M);
    float cb = fast_exp2(mb - M);
    const float inv = 1.0f / (la * ca + lb * cb);
    ca *= inv; cb *= inv;
    float4 va = ((const float4*)&g_pO[(size_t)row * Hh])[d4];
    float4 vb = ((const float4*)&g_pO[(size_t)(BT + row) * Hh])[d4];
    ((float4*)&out[(size_t)row * Hh])[d4] =
        make_float4(va.x * ca + vb.x * cb, va.y * ca + vb.y * cb,
                    va.z * ca + vb.z * cb, va.w * ca + vb.w * cb);
}

extern "C" void kernel_launch(void* const* d_in, const int* in_sizes, int n_in,
                              void* d_out, int out_size)
{
    const float* x  = (const float*)d_in[0];
    const float* Wk = (const float*)d_in[1];
    const float* Wq = (const float*)d_in[2];
    const float* Wv = (const float*)d_in[3];
    float* out = (float*)d_out;

    cudaFuncSetAttribute(proj_kernel, cudaFuncAttributeMaxDynamicSharedMemorySize, PROJ_SMEM);
    cudaFuncSetAttribute(attn_kernel, cudaFuncAttributeMaxDynamicSharedMemorySize, ATTN_SMEM);

    cvt_w_kernel<<<192 * Cc / 256, 256>>>(Wk, Wq, Wv);

    proj_kernel<<<BT / 64, 256, PROJ_SMEM>>>(x);

    dim3 ag(Tt / 64, 2, Bb);
    attn_kernel<<<ag, 256, ATTN_SMEM>>>();

    merge_kernel<<<BT * 16 / 256, 256>>>(out);
}

// round 11
// speedup vs baseline: 1.9124x; 1.5751x over previous
#include <cuda_runtime.h>
#include <cuda_fp16.h>

#define Bb 8
#define Tt 2048
#define Cc 1024
#define Hh 64
#define BT (Bb*Tt)

// fp16 scratch stored as 32-bit words (2 halves per word)
// g_q16/g_k16: [token][32 dim-words], words PERMUTED within 8-word groups
//   (natural word w -> pos (w&~7)+2*(w&3)+((w>>2)&1), so (t, t+4) pairs adjacent)
// g_q16 additionally has softmax scale * log2(e) folded in.
__device__ unsigned g_q16[BT*32];
__device__ unsigned g_k16[BT*32];
// g_vT16: [dim 64][BT/2 token-words], tokens permuted within 16-token groups
__device__ unsigned g_vT16[64*(BT/2)];
// fused W (Wk|Wq|Wv) fp16: [n 192][512 k-words], words permuted per 8-group
__device__ unsigned g_wh16[192*512];
// split-KV partials
__device__ float g_pO[2*BT*Hh];
__device__ float g_pm[2*BT];
__device__ float g_pl[2*BT];

#define WPERM(w) (((w) & ~7) + 2*((w) & 3) + (((w) >> 2) & 1))

__device__ __forceinline__ float fast_exp2(float x){
    float y;
    asm("ex2.approx.ftz.f32 %0, %1;" : "=f"(y) : "f"(x));
    return y;
}
__device__ __forceinline__ unsigned packh2(float lo, float hi){
    __half2 h = __floats2half2_rn(lo, hi);
    return *(unsigned*)&h;
}
__device__ __forceinline__ void mma_f16(float c[4], const unsigned a[4], const unsigned b[2]){
    asm volatile("mma.sync.aligned.m16n8k16.row.col.f32.f16.f16.f32 "
        "{%0,%1,%2,%3}, {%4,%5,%6,%7}, {%8,%9}, {%0,%1,%2,%3};"
        : "+f"(c[0]), "+f"(c[1]), "+f"(c[2]), "+f"(c[3])
        : "r"(a[0]), "r"(a[1]), "r"(a[2]), "r"(a[3]), "r"(b[0]), "r"(b[1]));
}
__device__ __forceinline__ void cp16(unsigned dst, const void* src){
    asm volatile("cp.async.cg.shared.global [%0], [%1], 16;" :: "r"(dst), "l"(src));
}
__device__ __forceinline__ void cp_commit(){ asm volatile("cp.async.commit_group;"); }
__device__ __forceinline__ void cp_wait0(){ asm volatile("cp.async.wait_group 0;"); }
__device__ __forceinline__ void cp_wait1(){ asm volatile("cp.async.wait_group 1;"); }
__device__ __forceinline__ void bar_sync(int id){
    asm volatile("bar.sync %0, 128;" :: "r"(id));
}
// token -> permuted half-position within g_vT rows (perm within 16-token groups)
__device__ __forceinline__ int tok_half_pos(int T){
    int wnat = (T >> 1) & 7;
    int pp = 2*(wnat & 3) + (wnat >> 2);
    return (T & ~15) + pp*2 + (T & 1);
}

// ---------------------------------------------------------------------------
// One-shot W fuse + fp16 + transpose-to-[n][k] + word permutation.
// idx: n fast (coalesced reads of W rows 2w, 2w+1).
// ---------------------------------------------------------------------------
__global__ __launch_bounds__(256) void cvt_w_kernel(
    const float* __restrict__ Wk,
    const float* __restrict__ Wq,
    const float* __restrict__ Wv)
{
    const int idx = blockIdx.x * 256 + threadIdx.x;   // 512*192 total
    const int n = idx % 192;
    const int w = idx / 192;                          // k-word 0..511
    const float* base = (n < 64) ? Wk : (n < 128) ? Wq : Wv;
    const int nn = (n < 64) ? n : (n < 128) ? n - 64 : n - 128;
    float lo = base[(size_t)(2*w)   * Hh + nn];
    float hi = base[(size_t)(2*w+1) * Hh + nn];
    g_wh16[(size_t)n * 512 + WPERM(w)] = packh2(lo, hi);
}

// ---------------------------------------------------------------------------
// Fused projection: [BT x 1024] @ W[1024 x 192], fp16 m16n8k16.
// 64x192 tile/block, 256 threads = 8 warps (2m x 4n), warp tile 32x48.
// x: registers -> transposed row-pair-permuted smem (fp16x2 words), a = LDS.64.
// W: cp.async direct from permuted g_wh16, b = single LDS.64.
// Epilogue: q (scale folded) / k word-permuted fp16; v transposed fp16.
// ---------------------------------------------------------------------------
#define PXW 72                 // xsT stride words (==8 mod 32)
#define PXS (16*PXW)           // 1152 words per stage (16 k-words)
#define PWW 24                 // ws row stride words (==24 mod 32, phase-distinct)
#define PWS (192*PWW)          // 4608 words per stage
#define PROJ_SMEM ((2*PXS + 2*PWS)*4)   // 46080 B

__global__ __launch_bounds__(256, 2) void proj_kernel(const float* __restrict__ x)
{
    const int row0 = blockIdx.x * 64;
    const int tid  = threadIdx.x;
    const int warp = tid >> 5;
    const int lane = tid & 31;
    const int mw = warp >> 2;      // 0..1
    const int wn = warp & 3;       // 0..3
    const int g = lane >> 2;
    const int t = lane & 3;

    extern __shared__ float sm[];
    unsigned* const xsm = (unsigned*)sm;                 // 2 stages xsT
    unsigned* const wsm = (unsigned*)sm + 2 * PXS;       // 2 stages ws
    const unsigned smb  = (unsigned)__cvta_generic_to_shared(sm);
    const unsigned wsmb = smb + 2u * PXS * 4u;

    float c[2][6][4];
#pragma unroll
    for (int mf = 0; mf < 2; mf++)
#pragma unroll
        for (int nf = 0; nf < 6; nf++)
#pragma unroll
            for (int i = 0; i < 4; i++) c[mf][nf][i] = 0.f;

    // x: 64 rows x 32 k fp32 = 512 float4, 2 per thread
    const int xr  = tid & 63;
    const int xcg = tid >> 6;      // 0..3
    const int qr  = (xr & ~15) + 2 * (xr & 7) + ((xr >> 3) & 1);   // slot(row)

    float4 xv[2];
    auto ldg_x = [&](int kc){
#pragma unroll
        for (int u = 0; u < 2; u++) {
            int c4 = (xcg * 2 + u) * 4;
            xv[u] = *(const float4*)&x[(size_t)(row0 + xr) * Cc + kc + c4];
        }
    };
    auto sts_x = [&](int s){
        unsigned* xs = xsm + s * PXS;
#pragma unroll
        for (int u = 0; u < 2; u++) {
            int w0 = (xcg * 2 + u) * 2;          // word index (natural)
            xs[(w0 + 0) * PXW + qr] = packh2(xv[u].x, xv[u].y);
            xs[(w0 + 1) * PXW + qr] = packh2(xv[u].z, xv[u].w);
        }
    };
    auto cp_w = [&](int kcw, int s){             // kcw = word base = it*16
        const unsigned wb = wsmb + (unsigned)(s * PWS) * 4u;
#pragma unroll
        for (int u = 0; u < 3; u++) {
            int f = tid + 256 * u;               // 768: 192 rows x 4 cp16
            int rr = f >> 2, wd4 = (f & 3) * 4;
            cp16(wb + (unsigned)(rr * PWW + wd4) * 4u,
                 &g_wh16[(size_t)rr * 512 + kcw + wd4]);
        }
        cp_commit();
    };

    ldg_x(0); cp_w(0, 0); sts_x(0);

    for (int it = 0; it < Cc / 32; it++) {
        cp_wait0();
        __syncthreads();
        const bool more = (it + 1 < Cc / 32);
        if (more) { ldg_x((it + 1) * 32); cp_w((it + 1) * 16, (it + 1) & 1); }

        const unsigned* xs = xsm + (it & 1) * PXS;
        const unsigned* ws = wsm + (it & 1) * PWS;
#pragma unroll
        for (int ks = 0; ks < 2; ks++) {         // two k16 per 32-chunk
            const int k0 = ks * 8;
            unsigned b[6][2];
#pragma unroll
            for (int nf = 0; nf < 6; nf++) {
                uint2 bb = *(const uint2*)&ws[(wn * 48 + nf * 8 + g) * PWW + k0 + 2 * t];
                b[nf][0] = bb.x; b[nf][1] = bb.y;
            }
#pragma unroll
            for (int mf = 0; mf < 2; mf++) {
                const int sbase = mw * 32 + mf * 16 + 2 * g;
                uint2 a01 = *(const uint2*)&xs[(k0 + t) * PXW + sbase];     // rows g,g+8 word t
                uint2 a23 = *(const uint2*)&xs[(k0 + t + 4) * PXW + sbase]; // word t+4
                unsigned a[4] = { a01.x, a01.y, a23.x, a23.y };
#pragma unroll
                for (int nf = 0; nf < 6; nf++) mma_f16(c[mf][nf], a, b[nf]);
            }
        }
        if (more) sts_x((it + 1) & 1);
    }

    // epilogue: fp16 conversions; q scale-folded; k/q word-permuted; v transposed
    const float QS = 0.125f * 1.44269504088896340736f;
    __half* const vth = (__half*)g_vT16;
#pragma unroll
    for (int mf = 0; mf < 2; mf++) {
        const int r0 = row0 + mw * 32 + mf * 16 + g;
#pragma unroll
        for (int nf = 0; nf < 6; nf++) {
            const int col = wn * 48 + nf * 8 + 2 * t;
            float v0 = c[mf][nf][0], v1 = c[mf][nf][1];
            float v2 = c[mf][nf][2], v3 = c[mf][nf][3];
            if (col < 64) {
                const int wp = WPERM(col >> 1);
                g_k16[(size_t)r0 * 32 + wp]       = packh2(v0, v1);
                g_k16[(size_t)(r0 + 8) * 32 + wp] = packh2(v2, v3);
            } else if (col < 128) {
                const int wp = WPERM((col - 64) >> 1);
                g_q16[(size_t)r0 * 32 + wp]       = packh2(v0 * QS, v1 * QS);
                g_q16[(size_t)(r0 + 8) * 32 + wp] = packh2(v2 * QS, v3 * QS);
            } else {
                const int d0 = col - 128;
                const int p0 = tok_half_pos(r0), p1 = tok_half_pos(r0 + 8);
                vth[(size_t)d0 * BT + p0]       = __float2half_rn(v0);
                vth[(size_t)(d0 + 1) * BT + p0] = __float2half_rn(v1);
                vth[(size_t)d0 * BT + p1]       = __float2half_rn(v2);
                vth[(size_t)(d0 + 1) * BT + p1] = __float2half_rn(v3);
            }
        }
    }
}

// ---------------------------------------------------------------------------
// Flash attention, fp16 m16n8k16. Split-KV x2 at block level + dual group.
// grid (32, 2, 8), 256 threads. P C-frags pack DIRECTLY into A-frags (fp16x2).
// K smem [key][32w perm]; V smem TRANSPOSED [dim][32 key-words perm].
// Writes unnormalized partials; merge_kernel finalizes.
// ---------------------------------------------------------------------------
#define AW 40                  // K/VsT row stride words (==8 mod 32)
#define ATILE (64*AW)          // 2560 words
#define ATTN_SMEM (4*ATILE*4)  // 40960 B  (2 groups x (K, VsT))

__global__ __launch_bounds__(256, 2) void attn_kernel()
{
    const int qt   = (int)gridDim.x - 1 - (int)blockIdx.x;   // heavy first
    const int half = blockIdx.y;
    const int b    = blockIdx.z;
    const int q0   = qt * 64;
    const int tid  = threadIdx.x;
    const int warp = tid >> 5;
    const int lane = tid & 31;
    const int group = warp >> 2;
    const int wl   = warp & 3;
    const int wr0  = wl * 16;
    const int g = lane >> 2;
    const int t = lane & 3;
    const int gtid = tid & 127;

    extern __shared__ float sm[];
    const unsigned smb = (unsigned)__cvta_generic_to_shared(sm);

    // q A-frags: 4 k16-chunks x 4 regs, loaded via LDG.64 (scale pre-folded)
    unsigned qa[4][4];
    {
        const size_t rA = (size_t)b * Tt + q0 + wr0 + g;
#pragma unroll
        for (int kc = 0; kc < 4; kc++) {
            uint2 lo = *(const uint2*)&g_q16[rA * 32 + kc * 8 + 2 * t];
            uint2 hi = *(const uint2*)&g_q16[(rA + 8) * 32 + kc * 8 + 2 * t];
            qa[kc][0] = lo.x; qa[kc][2] = lo.y;
            qa[kc][1] = hi.x; qa[kc][3] = hi.y;
        }
    }

    float oc[8][4];
#pragma unroll
    for (int nf = 0; nf < 8; nf++)
#pragma unroll
        for (int i = 0; i < 4; i++) oc[nf][i] = 0.f;
    float m0 = -1e30f, m1 = -1e30f, l0 = 0.f, l1 = 0.f;

    const unsigned kb = smb + (unsigned)(group * 2 * ATILE) * 4u;
    const unsigned vb = kb + ATILE * 4u;

    auto load_k = [&](int n0){
        const size_t base = ((size_t)b * Tt + n0) * 32;
#pragma unroll
        for (int u = 0; u < 4; u++) {
            int f = gtid + 128 * u;                  // 512: 64 keys x 4 cp16
            int row = f >> 3, wd4 = (f & 7) * 4;
            cp16(kb + (unsigned)(row * AW + wd4) * 4u, &g_k16[base + (size_t)row * 32 + wd4]);
        }
        cp_commit();
    };
    auto load_v = [&](int n0){
        const size_t base = (size_t)b * (Tt / 2) + n0 / 2;   // word base in row
#pragma unroll
        for (int u = 0; u < 4; u++) {
            int f = gtid + 128 * u;                  // 512: 64 dims x 4 cp16
            int row = f >> 3, wd4 = (f & 7) * 4;
            cp16(vb + (unsigned)(row * AW + wd4) * 4u,
                 &g_vT16[(size_t)row * (BT / 2) + base + wd4]);
        }
        cp_commit();
    };

    const int nt = qt + 1;
    const int s  = (half == 0) ? 0 : (nt + 1) / 2;
    const int e  = (half == 0) ? (nt + 1) / 2 : nt;
    const int ng = (e - s > group) ? ((e - s - group + 1) >> 1) : 0;

    if (ng > 0) { load_k((s + group) * 64); load_v((s + group) * 64); }

    const unsigned* Ks = (const unsigned*)sm + group * 2 * ATILE;
    const unsigned* Vs = Ks + ATILE;

    for (int j = 0; j < ng; j++) {
        const int tile = s + 2 * j + group;

        cp_wait1();               // own K ready
        bar_sync(1 + group);      // group K ready / prev Vs consumed by all

        float sc[8][4];
#pragma unroll
        for (int nf = 0; nf < 8; nf++)
#pragma unroll
            for (int i = 0; i < 4; i++) sc[nf][i] = 0.f;
#pragma unroll
        for (int kc = 0; kc < 4; kc++) {
#pragma unroll
            for (int nf = 0; nf < 8; nf++) {
                uint2 kk = *(const uint2*)&Ks[(nf * 8 + g) * AW + kc * 8 + 2 * t];
                unsigned bk[2] = { kk.x, kk.y };
                mma_f16(sc[nf], qa[kc], bk);
            }
        }
        bar_sync(1 + group);      // Ks consumed
        if (j + 1 < ng) load_k((tile + 2) * 64);

        if (tile == qt) {         // diagonal: causal mask
#pragma unroll
            for (int nf = 0; nf < 8; nf++) {
                const int kl = nf * 8 + 2 * t;
                if (kl     > wr0 + g)     sc[nf][0] = -1e30f;
                if (kl + 1 > wr0 + g)     sc[nf][1] = -1e30f;
                if (kl     > wr0 + g + 8) sc[nf][2] = -1e30f;
                if (kl + 1 > wr0 + g + 8) sc[nf][3] = -1e30f;
            }
        }

        float mx0 = -1e30f, mx1 = -1e30f;
#pragma unroll
        for (int nf = 0; nf < 8; nf++) {
            mx0 = fmaxf(mx0, fmaxf(sc[nf][0], sc[nf][1]));
            mx1 = fmaxf(mx1, fmaxf(sc[nf][2], sc[nf][3]));
        }
        mx0 = fmaxf(mx0, __shfl_xor_sync(0xffffffffu, mx0, 1));
        mx0 = fmaxf(mx0, __shfl_xor_sync(0xffffffffu, mx0, 2));
        mx1 = fmaxf(mx1, __shfl_xor_sync(0xffffffffu, mx1, 1));
        mx1 = fmaxf(mx1, __shfl_xor_sync(0xffffffffu, mx1, 2));

        const float m0n = fmaxf(m0, mx0);
        const float m1n = fmaxf(m1, mx1);
        const float corr0 = fast_exp2(m0 - m0n);
        const float corr1 = fast_exp2(m1 - m1n);
        l0 *= corr0; l1 *= corr1;
#pragma unroll
        for (int nf = 0; nf < 8; nf++) {
            oc[nf][0] *= corr0; oc[nf][1] *= corr0;
            oc[nf][2] *= corr1; oc[nf][3] *= corr1;
        }
        // exp + pack: P C-frags -> fp16 A-frags directly (zero shuffles)
        unsigned pa[4][4];
#pragma unroll
        for (int h = 0; h < 4; h++) {
#pragma unroll
            for (int q2 = 0; q2 < 2; q2++) {
                const int nf = 2 * h + q2;
                float p0 = fast_exp2(sc[nf][0] - m0n);
                float p1 = fast_exp2(sc[nf][1] - m0n);
                float p2 = fast_exp2(sc[nf][2] - m1n);
                float p3 = fast_exp2(sc[nf][3] - m1n);
                l0 += p0 + p1;
                l1 += p2 + p3;
                pa[h][0 + 2 * q2] = packh2(p0, p1);   // row g  (a0 / a2)
                pa[h][1 + 2 * q2] = packh2(p2, p3);   // row g+8 (a1 / a3)
            }
        }
        m0 = m0n; m1 = m1n;

        cp_wait1();               // own V ready
        bar_sync(1 + group);      // group V ready

        // O += P V : VsT rows = dims, b-frag = one LDS.64 per (h, nf)
#pragma unroll
        for (int h = 0; h < 4; h++) {
#pragma unroll
            for (int nf = 0; nf < 8; nf++) {
                uint2 vv = *(const uint2*)&Vs[(nf * 8 + g) * AW + h * 8 + 2 * t];
                unsigned bv[2] = { vv.x, vv.y };
                mma_f16(oc[nf], pa[h], bv);
            }
        }
        bar_sync(1 + group);      // Vs consumed
        if (j + 1 < ng) load_v((tile + 2) * 64);
    }

    // ---- merge group partials, write block partial (unnormalized) ----
    __syncthreads();
    if (group == 1) {
        float* st = sm + (wl * 32 + lane) * 37;
#pragma unroll
        for (int nf = 0; nf < 8; nf++)
#pragma unroll
            for (int i = 0; i < 4; i++) st[nf * 4 + i] = oc[nf][i];
        st[32] = m0; st[33] = m1; st[34] = l0; st[35] = l1;
    }
    __syncthreads();
    if (group == 0) {
        const float* st = sm + (wl * 32 + lane) * 37;
        const float mb0 = st[32], mb1 = st[33], lb0 = st[34], lb1 = st[35];
        const float M0 = fmaxf(m0, mb0), M1 = fmaxf(m1, mb1);
        const float ca0 = fast_exp2(m0 - M0), cb0 = fast_exp2(mb0 - M0);
        const float ca1 = fast_exp2(m1 - M1), cb1 = fast_exp2(mb1 - M1);
        l0 = l0 * ca0 + lb0 * cb0;
        l1 = l1 * ca1 + lb1 * cb1;
#pragma unroll
        for (int nf = 0; nf < 8; nf++) {
            oc[nf][0] = oc[nf][0] * ca0 + st[nf * 4 + 0] * cb0;
            oc[nf][1] = oc[nf][1] * ca0 + st[nf * 4 + 1] * cb0;
            oc[nf][2] = oc[nf][2] * ca1 + st[nf * 4 + 2] * cb1;
            oc[nf][3] = oc[nf][3] * ca1 + st[nf * 4 + 3] * cb1;
        }
        l0 += __shfl_xor_sync(0xffffffffu, l0, 1);
        l0 += __shfl_xor_sync(0xffffffffu, l0, 2);
        l1 += __shfl_xor_sync(0xffffffffu, l1, 1);
        l1 += __shfl_xor_sync(0xffffffffu, l1, 2);

        const size_t row = (size_t)b * Tt + q0 + wr0 + g;
        float* po = g_pO + ((size_t)half * BT + row) * Hh;
#pragma unroll
        for (int nf = 0; nf < 8; nf++) {
            const int col = nf * 8 + 2 * t;
            *(float2*)&po[col]          = make_float2(oc[nf][0], oc[nf][1]);
            *(float2*)&po[8 * Hh + col] = make_float2(oc[nf][2], oc[nf][3]);
        }
        if (t == 0) {
            g_pm[half * BT + row] = M0;
            g_pl[half * BT + row] = l0;
            g_pm[half * BT + row + 8] = M1;
            g_pl[half * BT + row + 8] = l1;
        }
    }
}

// ---------------------------------------------------------------------------
// Merge the two KV halves + normalize. One float4 of one row per thread.
// ---------------------------------------------------------------------------
__global__ __launch_bounds__(256) void merge_kernel(float* __restrict__ out)
{
    const int idx = blockIdx.x * 256 + threadIdx.x;   // BT*16 total
    const int row = idx >> 4;
    const int d4  = idx & 15;
    const float ma = g_pm[row],      mb = g_pm[BT + row];
    const float la = g_pl[row],      lb = g_pl[BT + row];
    const float M  = fmaxf(ma, mb);
    float ca = fast_exp2(ma - M);
    float cb = fast_exp2(mb - M);
    const float inv = 1.0f / (la * ca + lb * cb);
    ca *= inv; cb *= inv;
    float4 va = ((const float4*)&g_pO[(size_t)row * Hh])[d4];
    float4 vb = ((const float4*)&g_pO[(size_t)(BT + row) * Hh])[d4];
    ((float4*)&out[(size_t)row * Hh])[d4] =
        make_float4(va.x * ca + vb.x * cb, va.y * ca + vb.y * cb,
                    va.z * ca + vb.z * cb, va.w * ca + vb.w * cb);
}

extern "C" void kernel_launch(void* const* d_in, const int* in_sizes, int n_in,
                              void* d_out, int out_size)
{
    const float* x  = (const float*)d_in[0];
    const float* Wk = (const float*)d_in[1];
    const float* Wq = (const float*)d_in[2];
    const float* Wv = (const float*)d_in[3];
    float* out = (float*)d_out;

    cudaFuncSetAttribute(proj_kernel, cudaFuncAttributeMaxDynamicSharedMemorySize, PROJ_SMEM);
    cudaFuncSetAttribute(attn_kernel, cudaFuncAttributeMaxDynamicSharedMemorySize, ATTN_SMEM);

    cvt_w_kernel<<<512 * 192 / 256, 256>>>(Wk, Wq, Wv);

    proj_kernel<<<BT / 64, 256, PROJ_SMEM>>>(x);

    dim3 ag(Tt / 64, 2, Bb);
    attn_kernel<<<ag, 256, ATTN_SMEM>>>();

    merge_kernel<<<BT * 16 / 256, 256>>>(out);
}